// round 2
// baseline (speedup 1.0000x reference)
#include <cuda_runtime.h>
#include <cuda_bf16.h>

// Problem constants (B=2, H=8, S=256, D=64)
#define BATCH 2
#define NHEAD 8
#define SEQ   256
#define DIM   64

// Fused structure-attention kernel.
// grid = B*H*S blocks (one per query row), 256 threads/block.
//
// Pass 1: scores[k] = q . (key[k] + key_structure[q,k])   (warp-shuffle dot)
// softmax (with additive q-mask, then /sqrt(D)) in shared; attn written out.
// Pass 2: out[d] = sum_k attn[k] * (val[k,d] + val_structure[q,k,d])
__global__ __launch_bounds__(256, 8) void attn_struct_kernel(
    const float* __restrict__ q_,     // [B,H,S,D]
    const float* __restrict__ k_,     // [B,H,S,D]
    const float* __restrict__ v_,     // [B,H,S,D]
    const float* __restrict__ ks_,    // [B,H,S,S,D]
    const float* __restrict__ vs_,    // [B,H,S,S,D]
    const float* __restrict__ mask_,  // [B,S]
    float* __restrict__ out_,         // [B,H,S,D]
    float* __restrict__ attn_)        // [B,H,S,S]
{
    const int row  = blockIdx.x;         // (b*H + h)*S + q
    const int qidx = row & (SEQ - 1);
    const int bh   = row >> 8;           // b*H + h
    const int b    = bh / NHEAD;

    const int tid  = threadIdx.x;
    const int lane = tid & 31;
    const int warp = tid >> 5;

    __shared__ float sh_scores[SEQ];
    __shared__ float sh_red[8][DIM];
    __shared__ float sh_tmp[8];

    // ---- load q row (64 floats) into registers via shared ----
    __shared__ float sh_q[DIM];
    if (tid < DIM) sh_q[tid] = q_[(size_t)row * DIM + tid];
    __syncthreads();
    const float2 qv = *(const float2*)(sh_q + lane * 2);

    // ---- Pass 1: scores ----
    // warp w handles k in [w*32, w*32+32). Each k: lane loads float2 of
    // key_structure[row,k,:] (streaming) + key[bh,k,:] (L2-hot), fused dot.
    {
        const float* ksrow_base = ks_ + ((size_t)row * SEQ) * DIM;
        const float* krow_base  = k_  + ((size_t)bh  * SEQ) * DIM;
        #pragma unroll 4
        for (int i = 0; i < 32; ++i) {
            const int k = warp * 32 + i;
            float2 a = *(const float2*)(ksrow_base + (size_t)k * DIM + lane * 2);
            float2 c = *(const float2*)(krow_base  + (size_t)k * DIM + lane * 2);
            float s = (a.x + c.x) * qv.x + (a.y + c.y) * qv.y;
            #pragma unroll
            for (int off = 16; off >= 1; off >>= 1)
                s += __shfl_xor_sync(0xffffffffu, s, off);
            if (lane == 0) sh_scores[k] = s;
        }
    }
    __syncthreads();

    // ---- softmax over k (one score per thread) ----
    // mask indexed by q (faithful to reference broadcast [B,1,Sq,1]);
    // constant per row so softmax-invariant, but applied anyway.
    const float mval = (1.0f - mask_[b * SEQ + qidx]) * -100000.0f;
    float sc = (sh_scores[tid] + mval) * 0.125f;   // 1/sqrt(64)

    // block max
    float m = sc;
    #pragma unroll
    for (int off = 16; off >= 1; off >>= 1)
        m = fmaxf(m, __shfl_xor_sync(0xffffffffu, m, off));
    if (lane == 0) sh_tmp[warp] = m;
    __syncthreads();
    if (warp == 0) {
        float mm = sh_tmp[lane & 7];
        #pragma unroll
        for (int off = 4; off >= 1; off >>= 1)
            mm = fmaxf(mm, __shfl_xor_sync(0xffffffffu, mm, off));
        if (lane == 0) sh_tmp[0] = mm;
    }
    __syncthreads();
    const float rowmax = sh_tmp[0];

    float e = __expf(sc - rowmax);
    float s = e;
    #pragma unroll
    for (int off = 16; off >= 1; off >>= 1)
        s += __shfl_xor_sync(0xffffffffu, s, off);
    __syncthreads();
    if (lane == 0) sh_tmp[warp] = s;
    __syncthreads();
    if (warp == 0) {
        float ss = sh_tmp[lane & 7];
        #pragma unroll
        for (int off = 4; off >= 1; off >>= 1)
            ss += __shfl_xor_sync(0xffffffffu, ss, off);
        if (lane == 0) sh_tmp[0] = ss;
    }
    __syncthreads();
    const float inv_sum = 1.0f / sh_tmp[0];

    const float attn_v = e * inv_sum;
    sh_scores[tid] = attn_v;
    attn_[(size_t)row * SEQ + tid] = attn_v;   // coalesced attn output
    __syncthreads();

    // ---- Pass 2: out[d] = sum_k attn[k]*(val[k,d] + val_structure[q,k,d]) ----
    // warp w handles k in [w*32, w*32+32); lane owns float2 at d = 2*lane.
    {
        const float* vbase  = v_  + ((size_t)bh  * SEQ) * DIM;
        const float* vsbase = vs_ + ((size_t)row * SEQ) * DIM;
        float2 acc = make_float2(0.0f, 0.0f);
        #pragma unroll 4
        for (int i = 0; i < 32; ++i) {
            const int k = warp * 32 + i;
            const float a = sh_scores[k];
            float2 vv = *(const float2*)(vbase  + (size_t)k * DIM + lane * 2);
            float2 sv = *(const float2*)(vsbase + (size_t)k * DIM + lane * 2);
            acc.x = fmaf(a, vv.x + sv.x, acc.x);
            acc.y = fmaf(a, vv.y + sv.y, acc.y);
        }
        sh_red[warp][lane * 2]     = acc.x;
        sh_red[warp][lane * 2 + 1] = acc.y;
    }
    __syncthreads();

    if (tid < DIM) {
        float r = 0.0f;
        #pragma unroll
        for (int w = 0; w < 8; ++w) r += sh_red[w][tid];
        out_[(size_t)row * DIM + tid] = r;
    }
}

extern "C" void kernel_launch(void* const* d_in, const int* in_sizes, int n_in,
                              void* d_out, int out_size) {
    const float* q    = (const float*)d_in[0];
    const float* k    = (const float*)d_in[1];
    const float* v    = (const float*)d_in[2];
    const float* ks   = (const float*)d_in[3];
    const float* vs   = (const float*)d_in[4];
    const float* mask = (const float*)d_in[5];

    float* out  = (float*)d_out;                              // [B,H,S,D]
    float* attn = out + (size_t)BATCH * NHEAD * SEQ * DIM;    // [B,H,S,S]

    const int nrows = BATCH * NHEAD * SEQ;   // 4096
    attn_struct_kernel<<<nrows, 256>>>(q, k, v, ks, vs, mask, out, attn);
}

// round 4
// speedup vs baseline: 1.0208x; 1.0208x over previous
#include <cuda_runtime.h>
#include <cuda_bf16.h>

// Problem constants (B=2, H=8, S=256, D=64)
#define BATCH 2
#define NHEAD 8
#define SEQ   256
#define DIM   64

// Fused structure-attention kernel, float4 edition.
// grid = B*H*S blocks (one per query row), 256 threads/block.
//
// Warp lane split: sub = lane&15 owns d-range [4*sub, 4*sub+4),
//                  half = lane>>4 selects one of 2 k-rows per iteration.
// Pass 1: scores[k] = q . (key[k] + key_structure[q,k])   (16-lane shuffle dot)
// softmax (additive q-mask, /sqrt(D)) in shared; attn written out.
// Pass 2: out[d] = sum_k attn[k] * (val[k,d] + val_structure[q,k,d])
__global__ __launch_bounds__(256, 8) void attn_struct_kernel(
    const float* __restrict__ q_,     // [B,H,S,D]
    const float* __restrict__ k_,     // [B,H,S,D]
    const float* __restrict__ v_,     // [B,H,S,D]
    const float* __restrict__ ks_,    // [B,H,S,S,D]
    const float* __restrict__ vs_,    // [B,H,S,S,D]
    const float* __restrict__ mask_,  // [B,S]
    float* __restrict__ out_,         // [B,H,S,D]
    float* __restrict__ attn_)        // [B,H,S,S]
{
    const int row  = blockIdx.x;         // (b*H + h)*S + q
    const int qidx = row & (SEQ - 1);
    const int bh   = row >> 8;           // b*H + h
    const int b    = bh / NHEAD;

    const int tid  = threadIdx.x;
    const int lane = tid & 31;
    const int warp = tid >> 5;
    const int sub  = lane & 15;          // d/4 slot
    const int half = lane >> 4;          // which of 2 k-rows

    __shared__ float sh_scores[SEQ];
    __shared__ float sh_red[8][DIM];
    __shared__ float sh_tmp[8];
    __shared__ float sh_q[DIM];

    // ---- load q row (64 floats) ----
    if (tid < DIM) sh_q[tid] = q_[(size_t)row * DIM + tid];
    __syncthreads();
    const float4 qv = *(const float4*)(sh_q + sub * 4);

    // ---- Pass 1: scores ----
    // warp w handles k in [w*32, w*32+32), 2 rows per iteration.
    {
        const float* ksrow = ks_ + ((size_t)row * SEQ) * DIM;
        const float* krow  = k_  + ((size_t)bh  * SEQ) * DIM;
        #pragma unroll 4
        for (int i = 0; i < 16; ++i) {
            const int k = warp * 32 + i * 2 + half;
            float4 a = __ldcs((const float4*)(ksrow + (size_t)k * DIM + sub * 4));
            float4 c = *(const float4*)(krow + (size_t)k * DIM + sub * 4);
            float s = (a.x + c.x) * qv.x + (a.y + c.y) * qv.y
                    + (a.z + c.z) * qv.z + (a.w + c.w) * qv.w;
            #pragma unroll
            for (int off = 8; off >= 1; off >>= 1)
                s += __shfl_xor_sync(0xffffffffu, s, off);
            if (sub == 0) sh_scores[k] = s;
        }
    }
    __syncthreads();

    // ---- softmax over k (one score per thread) ----
    // mask indexed by q (faithful to reference broadcast [B,1,Sq,1]).
    const float mval = (1.0f - mask_[b * SEQ + qidx]) * -100000.0f;
    float sc = (sh_scores[tid] + mval) * 0.125f;   // 1/sqrt(64)

    float m = sc;
    #pragma unroll
    for (int off = 16; off >= 1; off >>= 1)
        m = fmaxf(m, __shfl_xor_sync(0xffffffffu, m, off));
    if (lane == 0) sh_tmp[warp] = m;
    __syncthreads();
    if (warp == 0) {
        float mm = sh_tmp[lane & 7];
        #pragma unroll
        for (int off = 4; off >= 1; off >>= 1)
            mm = fmaxf(mm, __shfl_xor_sync(0xffffffffu, mm, off));
        if (lane == 0) sh_tmp[0] = mm;
    }
    __syncthreads();
    const float rowmax = sh_tmp[0];

    float e = __expf(sc - rowmax);
    float s = e;
    #pragma unroll
    for (int off = 16; off >= 1; off >>= 1)
        s += __shfl_xor_sync(0xffffffffu, s, off);
    __syncthreads();
    if (lane == 0) sh_tmp[warp] = s;
    __syncthreads();
    if (warp == 0) {
        float ss = sh_tmp[lane & 7];
        #pragma unroll
        for (int off = 4; off >= 1; off >>= 1)
            ss += __shfl_xor_sync(0xffffffffu, ss, off);
        if (lane == 0) sh_tmp[0] = ss;
    }
    __syncthreads();
    const float inv_sum = 1.0f / sh_tmp[0];

    const float attn_v = e * inv_sum;
    sh_scores[tid] = attn_v;
    attn_[(size_t)row * SEQ + tid] = attn_v;   // coalesced attn output
    __syncthreads();

    // ---- Pass 2: out[d] = sum_k attn[k]*(val[k,d] + val_structure[q,k,d]) ----
    {
        const float* vbase  = v_  + ((size_t)bh  * SEQ) * DIM;
        const float* vsbase = vs_ + ((size_t)row * SEQ) * DIM;
        float4 acc = make_float4(0.0f, 0.0f, 0.0f, 0.0f);
        #pragma unroll 4
        for (int i = 0; i < 16; ++i) {
            const int k = warp * 32 + i * 2 + half;
            const float a = sh_scores[k];
            float4 vv = *(const float4*)(vbase + (size_t)k * DIM + sub * 4);
            float4 sv = __ldcs((const float4*)(vsbase + (size_t)k * DIM + sub * 4));
            acc.x = fmaf(a, vv.x + sv.x, acc.x);
            acc.y = fmaf(a, vv.y + sv.y, acc.y);
            acc.z = fmaf(a, vv.z + sv.z, acc.z);
            acc.w = fmaf(a, vv.w + sv.w, acc.w);
        }
        // fold the two k-halves together (lanes sub and sub+16 share d-range)
        acc.x += __shfl_xor_sync(0xffffffffu, acc.x, 16);
        acc.y += __shfl_xor_sync(0xffffffffu, acc.y, 16);
        acc.z += __shfl_xor_sync(0xffffffffu, acc.z, 16);
        acc.w += __shfl_xor_sync(0xffffffffu, acc.w, 16);
        if (half == 0)
            *(float4*)(&sh_red[warp][sub * 4]) = acc;
    }
    __syncthreads();

    if (tid < DIM) {
        float r = 0.0f;
        #pragma unroll
        for (int w = 0; w < 8; ++w) r += sh_red[w][tid];
        out_[(size_t)row * DIM + tid] = r;
    }
}

extern "C" void kernel_launch(void* const* d_in, const int* in_sizes, int n_in,
                              void* d_out, int out_size) {
    const float* q    = (const float*)d_in[0];
    const float* k    = (const float*)d_in[1];
    const float* v    = (const float*)d_in[2];
    const float* ks   = (const float*)d_in[3];
    const float* vs   = (const float*)d_in[4];
    const float* mask = (const float*)d_in[5];

    float* out  = (float*)d_out;                              // [B,H,S,D]
    float* attn = out + (size_t)BATCH * NHEAD * SEQ * DIM;    // [B,H,S,S]

    const int nrows = BATCH * NHEAD * SEQ;   // 4096
    attn_struct_kernel<<<nrows, 256>>>(q, k, v, ks, vs, mask, out, attn);
}

// round 7
// speedup vs baseline: 1.1951x; 1.1707x over previous
#include <cuda_runtime.h>
#include <cuda_bf16.h>

// Problem constants (B=2, H=8, S=256, D=64)
#define BATCH 2
#define NHEAD 8
#define SEQ   256
#define DIM   64

// Fused structure-attention kernel. 128 threads/block (4 warps), 8 CTAs/SM,
// 64 regs/thread for deep load batching (MLP).
// grid = B*H*S blocks (one per query row).
//
// Warp lane split: sub = lane&15 owns d-range [4*sub, 4*sub+4),
//                  half = lane>>4 selects one of 2 k-rows per iteration.
// Each warp owns 64 k-rows: k in [warp*64, warp*64+64).
__global__ __launch_bounds__(128, 8) void attn_struct_kernel(
    const float* __restrict__ q_,     // [B,H,S,D]
    const float* __restrict__ k_,     // [B,H,S,D]
    const float* __restrict__ v_,     // [B,H,S,D]
    const float* __restrict__ ks_,    // [B,H,S,S,D]
    const float* __restrict__ vs_,    // [B,H,S,S,D]
    const float* __restrict__ mask_,  // [B,S]
    float* __restrict__ out_,         // [B,H,S,D]
    float* __restrict__ attn_)        // [B,H,S,S]
{
    const int row  = blockIdx.x;         // (b*H + h)*S + q
    const int qidx = row & (SEQ - 1);
    const int bh   = row >> 8;           // b*H + h
    const int b    = bh / NHEAD;

    const int tid  = threadIdx.x;        // 0..127
    const int lane = tid & 31;
    const int warp = tid >> 5;           // 0..3
    const int sub  = lane & 15;          // d/4 slot
    const int half = lane >> 4;          // which of 2 k-rows

    __shared__ float sh_scores[SEQ];
    __shared__ float sh_red[4][DIM];
    __shared__ float sh_tmp[4];
    __shared__ float sh_q[DIM];

    // ---- load q row (64 floats) ----
    if (tid < DIM) sh_q[tid] = q_[(size_t)row * DIM + tid];
    __syncthreads();
    const float4 qv = *(const float4*)(sh_q + sub * 4);

    // ---- Pass 1: scores[k] = q . (key[k] + key_structure[q,k]) ----
    {
        const float* ksrow = ks_ + ((size_t)row * SEQ) * DIM
                                 + ((size_t)(warp * 64 + half)) * DIM + sub * 4;
        const float* krow  = k_  + ((size_t)bh  * SEQ) * DIM
                                 + ((size_t)(warp * 64 + half)) * DIM + sub * 4;
        #pragma unroll 4
        for (int i = 0; i < 32; ++i) {
            const int k = warp * 64 + i * 2 + half;
            float4 a = __ldcs((const float4*)(ksrow + (size_t)i * 2 * DIM));
            float4 c = *(const float4*)(krow + (size_t)i * 2 * DIM);
            float s = (a.x + c.x) * qv.x + (a.y + c.y) * qv.y
                    + (a.z + c.z) * qv.z + (a.w + c.w) * qv.w;
            #pragma unroll
            for (int off = 8; off >= 1; off >>= 1)
                s += __shfl_xor_sync(0xffffffffu, s, off);
            if (sub == 0) sh_scores[k] = s;
        }
    }
    __syncthreads();

    // ---- softmax over 256 scores, 128 threads (2 scores/thread) ----
    const float mval = (1.0f - mask_[b * SEQ + qidx]) * -100000.0f;
    float sc0 = (sh_scores[tid]       + mval) * 0.125f;   // 1/sqrt(64)
    float sc1 = (sh_scores[tid + 128] + mval) * 0.125f;

    float m = fmaxf(sc0, sc1);
    #pragma unroll
    for (int off = 16; off >= 1; off >>= 1)
        m = fmaxf(m, __shfl_xor_sync(0xffffffffu, m, off));
    if (lane == 0) sh_tmp[warp] = m;
    __syncthreads();
    if (warp == 0) {
        float mm = sh_tmp[lane & 3];
        #pragma unroll
        for (int off = 2; off >= 1; off >>= 1)
            mm = fmaxf(mm, __shfl_xor_sync(0xffffffffu, mm, off));
        if (lane == 0) sh_tmp[0] = mm;
    }
    __syncthreads();
    const float rowmax = sh_tmp[0];

    float e0 = __expf(sc0 - rowmax);
    float e1 = __expf(sc1 - rowmax);
    float s = e0 + e1;
    #pragma unroll
    for (int off = 16; off >= 1; off >>= 1)
        s += __shfl_xor_sync(0xffffffffu, s, off);
    __syncthreads();
    if (lane == 0) sh_tmp[warp] = s;
    __syncthreads();
    if (warp == 0) {
        float ss = sh_tmp[lane & 3];
        #pragma unroll
        for (int off = 2; off >= 1; off >>= 1)
            ss += __shfl_xor_sync(0xffffffffu, ss, off);
        if (lane == 0) sh_tmp[0] = ss;
    }
    __syncthreads();
    const float inv_sum = 1.0f / sh_tmp[0];

    const float a0 = e0 * inv_sum;
    const float a1 = e1 * inv_sum;
    sh_scores[tid]       = a0;
    sh_scores[tid + 128] = a1;
    attn_[(size_t)row * SEQ + tid]       = a0;   // coalesced attn output
    attn_[(size_t)row * SEQ + tid + 128] = a1;
    __syncthreads();

    // ---- Pass 2: out[d] = sum_k attn[k]*(val[k,d] + val_structure[q,k,d]) ----
    {
        const float* vbase  = v_  + ((size_t)bh  * SEQ) * DIM
                                  + ((size_t)(warp * 64 + half)) * DIM + sub * 4;
        const float* vsbase = vs_ + ((size_t)row * SEQ) * DIM
                                  + ((size_t)(warp * 64 + half)) * DIM + sub * 4;
        float4 acc = make_float4(0.0f, 0.0f, 0.0f, 0.0f);
        #pragma unroll 4
        for (int i = 0; i < 32; ++i) {
            const int k = warp * 64 + i * 2 + half;
            const float a = sh_scores[k];
            float4 vv = *(const float4*)(vbase + (size_t)i * 2 * DIM);
            float4 sv = __ldcs((const float4*)(vsbase + (size_t)i * 2 * DIM));
            acc.x = fmaf(a, vv.x + sv.x, acc.x);
            acc.y = fmaf(a, vv.y + sv.y, acc.y);
            acc.z = fmaf(a, vv.z + sv.z, acc.z);
            acc.w = fmaf(a, vv.w + sv.w, acc.w);
        }
        // fold the two k-halves (lanes sub and sub+16 share d-range)
        acc.x += __shfl_xor_sync(0xffffffffu, acc.x, 16);
        acc.y += __shfl_xor_sync(0xffffffffu, acc.y, 16);
        acc.z += __shfl_xor_sync(0xffffffffu, acc.z, 16);
        acc.w += __shfl_xor_sync(0xffffffffu, acc.w, 16);
        if (half == 0)
            *(float4*)(&sh_red[warp][sub * 4]) = acc;
    }
    __syncthreads();

    if (tid < DIM) {
        float r = sh_red[0][tid] + sh_red[1][tid] + sh_red[2][tid] + sh_red[3][tid];
        out_[(size_t)row * DIM + tid] = r;
    }
}

extern "C" void kernel_launch(void* const* d_in, const int* in_sizes, int n_in,
                              void* d_out, int out_size) {
    const float* q    = (const float*)d_in[0];
    const float* k    = (const float*)d_in[1];
    const float* v    = (const float*)d_in[2];
    const float* ks   = (const float*)d_in[3];
    const float* vs   = (const float*)d_in[4];
    const float* mask = (const float*)d_in[5];

    float* out  = (float*)d_out;                              // [B,H,S,D]
    float* attn = out + (size_t)BATCH * NHEAD * SEQ * DIM;    // [B,H,S,S]

    const int nrows = BATCH * NHEAD * SEQ;   // 4096
    attn_struct_kernel<<<nrows, 128>>>(q, k, v, ks, vs, mask, out, attn);
}